// round 2
// baseline (speedup 1.0000x reference)
#include <cuda_runtime.h>

// SGC: out = S^2 (X w) + b, where S = D^-1/2 (A + I) D^-1/2 (normalized by in-degree
// over col). Projection commutes with propagation => propagate a scalar per node.

#define NN 100000
#define EE 600000
#define DD 128

// Scratch (no allocations allowed in kernel_launch)
__device__ float g_deg[NN];
__device__ float g_dis[NN];
__device__ float g_y0[NN];
__device__ float g_y1[NN];
__device__ int   g_is64;

// ---------------------------------------------------------------------------
// Detect whether edge_index is int64 or int32. JAX default config truncates
// the reference's requested int64 to int32; we can't see metadata, so sniff.
// If data were int32, the int64 view of element k has high word = index
// 2k+1 (random in [0,100000)); all-16 being < NN has prob ~1e-80.
__global__ void k_detect(const void* __restrict__ ei) {
    const long long* p = (const long long*)ei;
    int ok = 1;
    #pragma unroll
    for (int k = 0; k < 16; k++) {
        long long v = p[k];
        if (v < 0 || v >= (long long)NN) ok = 0;
    }
    g_is64 = ok;
}

__device__ __forceinline__ int load_idx(const void* ei, int e, int half, int is64) {
    if (is64) return (int)(((const long long*)ei)[(size_t)half * EE + e]);
    return ((const int*)ei)[half * EE + e];
}

// ---------------------------------------------------------------------------
__global__ void k_init_deg() {
    int i = blockIdx.x * blockDim.x + threadIdx.x;
    if (i < NN) g_deg[i] = 1.0f;          // self-loop
}

__global__ void k_deg(const void* __restrict__ ei) {
    int e = blockIdx.x * blockDim.x + threadIdx.x;
    if (e >= EE) return;
    int is64 = g_is64;
    int c = load_idx(ei, e, 1, is64);
    atomicAdd(&g_deg[c], 1.0f);
}

// One warp per node: y0[i] = dot(x[i,:], w); also finalize dis and the
// self-loop term of round 1: y1[i] = dis^2 * y0[i] = y0[i] / deg[i].
__global__ void k_dot(const float* __restrict__ x, const float* __restrict__ W) {
    int t = blockIdx.x * blockDim.x + threadIdx.x;
    int node = t >> 5;
    int lane = t & 31;
    if (node >= NN) return;
    float4 xv = __ldg(((const float4*)(x + (size_t)node * DD)) + lane);
    float4 wv = __ldg(((const float4*)W) + lane);
    float s = xv.x * wv.x + xv.y * wv.y + xv.z * wv.z + xv.w * wv.w;
    #pragma unroll
    for (int o = 16; o; o >>= 1) s += __shfl_xor_sync(0xffffffffu, s, o);
    if (lane == 0) {
        float deg = g_deg[node];
        g_dis[node] = rsqrtf(deg);
        g_y0[node]  = s;
        g_y1[node]  = s / deg;           // self-loop contribution, round 1
    }
}

// Round 1 edges: y1[c] += dis[r]*dis[c]*y0[r]
__global__ void k_prop1(const void* __restrict__ ei) {
    int e = blockIdx.x * blockDim.x + threadIdx.x;
    if (e >= EE) return;
    int is64 = g_is64;
    int r = load_idx(ei, e, 0, is64);
    int c = load_idx(ei, e, 1, is64);
    atomicAdd(&g_y1[c], g_dis[r] * g_dis[c] * g_y0[r]);
}

// Round 2 self-loop + bias, written straight into d_out.
__global__ void k_self2(float* __restrict__ out, const float* __restrict__ b) {
    int i = blockIdx.x * blockDim.x + threadIdx.x;
    if (i >= NN) return;
    float dis = g_dis[i];
    out[i] = dis * dis * g_y1[i] + b[0];
}

// Round 2 edges: out[c] += dis[r]*dis[c]*y1[r]
__global__ void k_prop2(const void* __restrict__ ei, float* __restrict__ out) {
    int e = blockIdx.x * blockDim.x + threadIdx.x;
    if (e >= EE) return;
    int is64 = g_is64;
    int r = load_idx(ei, e, 0, is64);
    int c = load_idx(ei, e, 1, is64);
    atomicAdd(&out[c], g_dis[r] * g_dis[c] * g_y1[r]);
}

// ---------------------------------------------------------------------------
extern "C" void kernel_launch(void* const* d_in, const int* in_sizes, int n_in,
                              void* d_out, int out_size) {
    const float* x  = (const float*)d_in[0];
    const void*  ei = d_in[1];
    const float* W  = (const float*)d_in[2];
    const float* b  = (const float*)d_in[3];
    float* out = (float*)d_out;

    const int TB = 256;
    k_detect<<<1, 1>>>(ei);
    k_init_deg<<<(NN + TB - 1) / TB, TB>>>();
    k_deg<<<(EE + TB - 1) / TB, TB>>>(ei);
    k_dot<<<(NN * 32 + TB - 1) / TB, TB>>>(x, W);
    k_prop1<<<(EE + TB - 1) / TB, TB>>>(ei);
    k_self2<<<(NN + TB - 1) / TB, TB>>>(out, b);
    k_prop2<<<(EE + TB - 1) / TB, TB>>>(ei, out);
}

// round 4
// speedup vs baseline: 1.2310x; 1.2310x over previous
#include <cuda_runtime.h>

// SGC: out = S^2 (X w) + b,  S = D^-1/2 (A+I) D^-1/2.
// Projection commutes with propagation => propagate ONE scalar per node.
// Factor dis[c] out of edge loop:  t[c] = sum_r z[r],  z = dis*y.
//   y1  = dis*t1 + y0/deg        (self loop term: dis^2*y0 = y0/deg)
//   z1  = dis*y1
//   out = dis*t2 + dis^2*y1 + b = dis*(t2 + z1) + b

#define NN 100000
#define EE 600000
#define DD 128

__device__ float g_deg[NN];
__device__ float g_dis[NN];
__device__ float g_z0[NN];      // dis * y0
__device__ float g_y1s[NN];     // y0 / deg  (round-1 self-loop term)
__device__ float g_z1[NN];      // dis * y1
__device__ float g_t1[NN];
__device__ float g_t2[NN];
__device__ int   g_is64;

// ---------------------------------------------------------------------------
// init: deg=1 (self loop), t1=t2=0; thread 0 sniffs int64 vs int32 edge dtype.
// (int32 data viewed as int64 puts a random node index in the high word —
//  16 consecutive false positives has prob ~1e-80.)
__global__ void k_init(const void* __restrict__ ei) {
    int i = blockIdx.x * blockDim.x + threadIdx.x;
    if (i < NN) { g_deg[i] = 1.0f; g_t1[i] = 0.0f; g_t2[i] = 0.0f; }
    if (i == 0) {
        const long long* p = (const long long*)ei;
        int ok = 1;
        #pragma unroll
        for (int k = 0; k < 16; k++) {
            long long v = p[k];
            if (v < 0 || v >= (long long)NN) ok = 0;
        }
        g_is64 = ok;
    }
}

__device__ __forceinline__ int load_idx(const void* ei, int e, int half, int is64) {
    if (is64) return (int)(((const long long*)ei)[(size_t)half * EE + e]);
    return ((const int*)ei)[half * EE + e];
}

__global__ void k_deg(const void* __restrict__ ei) {
    int e = blockIdx.x * blockDim.x + threadIdx.x;
    if (e >= EE) return;
    atomicAdd(&g_deg[load_idx(ei, e, 1, g_is64)], 1.0f);
}

// ---------------------------------------------------------------------------
// 4 nodes per warp: batch 4 independent float4 row loads (MLP=4) before the
// shuffle reductions.  NN % 4 == 0 so no per-warp tail.
__global__ void __launch_bounds__(256) k_dot(const float* __restrict__ x,
                                             const float* __restrict__ W) {
    int t = blockIdx.x * blockDim.x + threadIdx.x;
    int warp = t >> 5;
    int lane = t & 31;
    int base = warp * 4;
    if (base >= NN) return;
    float4 wv = __ldg(((const float4*)W) + lane);

    float4 xv[4];
    #pragma unroll
    for (int j = 0; j < 4; j++)
        xv[j] = __ldg(((const float4*)(x + (size_t)(base + j) * DD)) + lane);

    float s0 = xv[0].x * wv.x + xv[0].y * wv.y + xv[0].z * wv.z + xv[0].w * wv.w;
    float s1 = xv[1].x * wv.x + xv[1].y * wv.y + xv[1].z * wv.z + xv[1].w * wv.w;
    float s2 = xv[2].x * wv.x + xv[2].y * wv.y + xv[2].z * wv.z + xv[2].w * wv.w;
    float s3 = xv[3].x * wv.x + xv[3].y * wv.y + xv[3].z * wv.z + xv[3].w * wv.w;

    #pragma unroll
    for (int o = 16; o; o >>= 1) {
        s0 += __shfl_xor_sync(0xffffffffu, s0, o);
        s1 += __shfl_xor_sync(0xffffffffu, s1, o);
        s2 += __shfl_xor_sync(0xffffffffu, s2, o);
        s3 += __shfl_xor_sync(0xffffffffu, s3, o);
    }

    if (lane < 4) {                     // lane j finalizes node base+j
        float y0 = (lane == 0) ? s0 : (lane == 1) ? s1 : (lane == 2) ? s2 : s3;
        int node = base + lane;
        float deg = g_deg[node];
        float dis = rsqrtf(deg);
        g_dis[node] = dis;
        g_z0[node]  = dis * y0;
        g_y1s[node] = y0 / deg;
    }
}

// Edge scatter: dst[c] += src[r].  One gather + one atomic per edge.
// Globals selected at COMPILE TIME — device symbols must not cross the
// host kernel-arg boundary.
template <int PASS>
__global__ void k_pass(const void* __restrict__ ei) {
    int e = blockIdx.x * blockDim.x + threadIdx.x;
    if (e >= EE) return;
    int is64 = g_is64;
    int r = load_idx(ei, e, 0, is64);
    int c = load_idx(ei, e, 1, is64);
    if (PASS == 1) atomicAdd(&g_t1[c], g_z0[r]);
    else           atomicAdd(&g_t2[c], g_z1[r]);
}

// z1 = dis * (dis*t1 + y0/deg)
__global__ void k_mid() {
    int i = blockIdx.x * blockDim.x + threadIdx.x;
    if (i >= NN) return;
    float dis = g_dis[i];
    g_z1[i] = dis * (dis * g_t1[i] + g_y1s[i]);
}

// out = dis*(t2 + z1) + b
__global__ void k_final(float* __restrict__ out, const float* __restrict__ b) {
    int i = blockIdx.x * blockDim.x + threadIdx.x;
    if (i >= NN) return;
    out[i] = g_dis[i] * (g_t2[i] + g_z1[i]) + b[0];
}

// ---------------------------------------------------------------------------
extern "C" void kernel_launch(void* const* d_in, const int* in_sizes, int n_in,
                              void* d_out, int out_size) {
    const float* x  = (const float*)d_in[0];
    const void*  ei = d_in[1];
    const float* W  = (const float*)d_in[2];
    const float* b  = (const float*)d_in[3];
    float* out = (float*)d_out;

    const int TB = 256;
    k_init   <<<(NN + TB - 1) / TB, TB>>>(ei);
    k_deg    <<<(EE + TB - 1) / TB, TB>>>(ei);
    k_dot    <<<(NN / 4 * 32 + TB - 1) / TB, TB>>>(x, W);
    k_pass<1><<<(EE + TB - 1) / TB, TB>>>(ei);
    k_mid    <<<(NN + TB - 1) / TB, TB>>>();
    k_pass<2><<<(EE + TB - 1) / TB, TB>>>(ei);
    k_final  <<<(NN + TB - 1) / TB, TB>>>(out, b);
}